// round 2
// baseline (speedup 1.0000x reference)
#include <cuda_runtime.h>
#include <math.h>

#define Bp 512      // particles
#define Dd 64       // dim
#define Cc 512      // channels
#define NBs 8       // steps
#define NHl 3       // hidden layers
#define MC 8        // mixture components
#define NBINS 131072
#define BIN_MAXD 64.0f

__device__ float g_hA[Bp*Cc];
__device__ float g_hB[Bp*Cc];
__device__ float g_score[Bp*Dd];
__device__ float g_d2[Bp*Bp];
__device__ float g_bias1[NBs*Cc];
__device__ float g_betas[NBs+1];
__device__ float g_ht;
__device__ int   g_hist[NBINS];

__device__ __forceinline__ float gelu_t(float x){
    float x3 = x*x*x;
    return 0.5f*x*(1.0f+tanhf(0.7978845608028654f*(x+0.044715f*x3)));
}

// block s computes the fused input-layer bias for step s (t = s).
// block 0 / thread 0 also computes betas; all threads help zero the histogram.
__global__ void setup_kernel(const float* __restrict__ grid_t, const float* __restrict__ phase,
                             const float* __restrict__ t_W1, const float* __restrict__ t_b1,
                             const float* __restrict__ t_W2, const float* __restrict__ t_b2,
                             const float* __restrict__ in_b){
    __shared__ float temb[2*Cc];
    __shared__ float g1[Cc];
    int c = threadIdx.x;
    int s = blockIdx.x;
    for (int idx = s*blockDim.x + c; idx < NBINS; idx += gridDim.x*blockDim.x) g_hist[idx] = 0;
    if (s == 0 && c == 0){
        float cum = 0.f;
        g_betas[0] = 0.f;
        for (int j = 0; j < NBs; j++){
            float sg = 1.f/(1.f+expf(-grid_t[j]));
            cum += sg;
            g_betas[j+1] = cum;
        }
        float inv = 1.f/cum;
        for (int j = 0; j <= NBs; j++) g_betas[j] *= inv;
    }
    float t = (float)s;
    float coeff = 0.1f + (float)c*(99.9f/511.0f);   // linspace(0.1, 100, 512)
    float e = coeff*t + phase[c];
    temb[c]      = sinf(e);
    temb[Cc+c]   = cosf(e);
    __syncthreads();
    float acc = t_b1[c];
    for (int k = 0; k < 2*Cc; k++) acc += temb[k]*t_W1[k*Cc+c];
    g1[c] = gelu_t(acc);
    __syncthreads();
    float acc2 = t_b2[c];
    for (int k = 0; k < Cc; k++) acc2 += g1[k]*t_W2[k*Cc+c];
    g_bias1[s*Cc+c] = acc2 + in_b[c];
}

// C = act(A[M,K] @ W[K,N] + bias), 64x64 tile per block, 256 threads, 4x4 microtile.
// biasStep >= 0 -> bias = g_bias1 + biasStep*Cc (fused te + in_b).
__global__ void gemm_kernel(const float* __restrict__ A, const float* __restrict__ W,
                            const float* __restrict__ bias, float* __restrict__ Cm,
                            int Mm, int Nn, int Kk, int act, int biasStep){
    __shared__ float As[16][64];
    __shared__ float Ws[16][64];
    int tid = threadIdx.x;
    int tx = tid & 15, ty = tid >> 4;
    int m0 = blockIdx.y*64, n0 = blockIdx.x*64;
    int ar = tid >> 2, aq = tid & 3;
    int wr = tid >> 4, wq = tid & 15;
    float acc[4][4] = {};
    for (int k0 = 0; k0 < Kk; k0 += 16){
        float4 av = *reinterpret_cast<const float4*>(&A[(size_t)(m0+ar)*Kk + k0 + aq*4]);
        As[aq*4+0][ar] = av.x; As[aq*4+1][ar] = av.y;
        As[aq*4+2][ar] = av.z; As[aq*4+3][ar] = av.w;
        float4 wv = *reinterpret_cast<const float4*>(&W[(size_t)(k0+wr)*Nn + n0 + wq*4]);
        *reinterpret_cast<float4*>(&Ws[wr][wq*4]) = wv;
        __syncthreads();
        #pragma unroll
        for (int kk = 0; kk < 16; kk++){
            float a[4], b[4];
            #pragma unroll
            for (int i = 0; i < 4; i++) a[i] = As[kk][ty*4+i];
            #pragma unroll
            for (int j = 0; j < 4; j++) b[j] = Ws[kk][tx*4+j];
            #pragma unroll
            for (int i = 0; i < 4; i++)
                #pragma unroll
                for (int j = 0; j < 4; j++) acc[i][j] += a[i]*b[j];
        }
        __syncthreads();
    }
    const float* bptr = (biasStep >= 0) ? (g_bias1 + biasStep*Cc) : bias;
    #pragma unroll
    for (int i = 0; i < 4; i++){
        int mrow = m0 + ty*4 + i;
        #pragma unroll
        for (int j = 0; j < 4; j++){
            int ncol = n0 + tx*4 + j;
            float v = acc[i][j] + bptr[ncol];
            if (act) v = gelu_t(v);
            Cm[(size_t)mrow*Nn + ncol] = v;
        }
    }
}

// pairwise squared distances (64x64 tile per block) + distance histogram
__global__ void pairwise_kernel(const float* __restrict__ x){
    __shared__ float ai[64][65];
    __shared__ float bj[64][65];
    int tid = threadIdx.x;
    int i0 = blockIdx.y*64, j0 = blockIdx.x*64;
    for (int t = tid; t < 4096; t += 256){
        int r = t >> 6, k = t & 63;
        ai[r][k] = x[(i0+r)*Dd + k];
        bj[r][k] = x[(j0+r)*Dd + k];
    }
    __syncthreads();
    int tx = tid & 15, ty = tid >> 4;
    float acc[4][4] = {};
    for (int k = 0; k < 64; k++){
        float a[4], b[4];
        #pragma unroll
        for (int i = 0; i < 4; i++) a[i] = ai[ty*4+i][k];
        #pragma unroll
        for (int j = 0; j < 4; j++) b[j] = bj[tx*4+j][k];
        #pragma unroll
        for (int i = 0; i < 4; i++)
            #pragma unroll
            for (int j = 0; j < 4; j++){
                float df = a[i]-b[j];
                acc[i][j] += df*df;
            }
    }
    const float sc = (float)NBINS / BIN_MAXD;
    #pragma unroll
    for (int i = 0; i < 4; i++){
        int gi = i0 + ty*4 + i;
        #pragma unroll
        for (int j = 0; j < 4; j++){
            int gj = j0 + tx*4 + j;
            float d2 = acc[i][j];
            g_d2[gi*Bp + gj] = d2;
            float dist = sqrtf(d2 > 0.f ? d2 : 1e-12f);
            int bin = (int)(dist*sc);
            if (bin > NBINS-1) bin = NBINS-1;
            atomicAdd(&g_hist[bin], 1);
        }
    }
}

// exact rank selection of the median from the histogram, then re-zero it
__global__ void median_kernel(){
    __shared__ int cnt[1024];
    int tid = threadIdx.x;
    int base = tid*128;
    int s = 0;
    for (int b = 0; b < 128; b++) s += g_hist[base+b];
    cnt[tid] = s;
    __syncthreads();
    if (tid == 0){
        long long ks[2] = {(long long)Bp*Bp/2, (long long)Bp*Bp/2 + 1};
        float v[2];
        for (int q = 0; q < 2; q++){
            long long cum = 0;
            int ch = 0;
            while (ch < 1024 && cum + cnt[ch] < ks[q]){ cum += cnt[ch]; ch++; }
            int bin = ch*128;
            int lim = bin + 128;
            while (bin < lim){ cum += g_hist[bin]; if (cum >= ks[q]) break; bin++; }
            v[q] = ((float)bin + 0.5f) * (BIN_MAXD/(float)NBINS);
        }
        float med = 0.5f*(v[0]+v[1]);
        g_ht = med*med / logf((float)Bp);
    }
    __syncthreads();
    for (int b = 0; b < 128; b++) g_hist[base+b] = 0;
}

// fused: mixture softmax -> grad log pi, RBF repulsion, Langevin update
__global__ void update_kernel(const float* __restrict__ x, const float* __restrict__ noises,
                              const float* __restrict__ means, const float* __restrict__ eps,
                              int step, float* __restrict__ xn){
    __shared__ float xi[Dd];
    __shared__ float w[Bp];
    __shared__ float compm[MC];
    __shared__ float wm[MC];
    int i = blockIdx.x, d = threadIdx.x;
    xi[d] = x[i*Dd + d];
    __syncthreads();
    if (d < MC){
        float s = 0;
        for (int k = 0; k < Dd; k++){
            float df = xi[k] - means[d*Dd + k];
            s += df*df;
        }
        compm[d] = -0.5f*s;
    }
    __syncthreads();
    if (d == 0){
        float mx = compm[0];
        for (int m = 1; m < MC; m++) mx = fmaxf(mx, compm[m]);
        float se = 0;
        for (int m = 0; m < MC; m++){ float e = expf(compm[m]-mx); wm[m] = e; se += e; }
        float inv = 1.f/se;
        for (int m = 0; m < MC; m++) wm[m] *= inv;
    }
    __syncthreads();
    float ht = g_ht;
    float inv_ht = 1.f/ht;
    for (int j = d; j < Bp; j += Dd) w[j] = expf(-g_d2[i*Bp + j]*inv_ht);
    __syncthreads();
    float xd = xi[d];
    float wbar = 0;
    for (int m = 0; m < MC; m++) wbar += wm[m]*means[m*Dd + d];
    float r = 0;
    for (int j = 0; j < Bp; j++) r += w[j]*(xd - x[j*Dd + d]);
    float t  = g_betas[step];
    float dt = eps[0];
    float grad  = t*wbar - xd;                       // analytic grad log pi
    float drift = grad - g_score[i*Dd + d];
    float nv = noises[((size_t)step*Bp + i)*Dd + d];
    // new = x + dt*drift + sqrt(2dt)*noise - repel*dt, repel = -0.1/h_t * R
    float nw = xd + dt*drift + sqrtf(2.f*dt)*nv + (0.1f*dt*inv_ht)*r;
    xn[i*Dd + d] = nw;
}

extern "C" void kernel_launch(void* const* d_in, const int* in_sizes, int n_in,
                              void* d_out, int out_size){
    const float* particles = (const float*)d_in[0];
    const float* noises    = (const float*)d_in[1];
    const float* grid_t    = (const float*)d_in[2];
    const float* eps       = (const float*)d_in[3];
    const float* means     = (const float*)d_in[4];
    const float* phase     = (const float*)d_in[5];
    const float* in_W      = (const float*)d_in[6];
    const float* in_b      = (const float*)d_in[7];
    const float* t_W1      = (const float*)d_in[8];
    const float* t_b1      = (const float*)d_in[9];
    const float* t_W2      = (const float*)d_in[10];
    const float* t_b2      = (const float*)d_in[11];
    const float* h_W       = (const float*)d_in[12];
    const float* h_b       = (const float*)d_in[13];
    const float* out_W     = (const float*)d_in[14];
    const float* out_b     = (const float*)d_in[15];
    float* out = (float*)d_out;

    // slice 0 = initial particles
    cudaMemcpyAsync(out, particles, (size_t)Bp*Dd*sizeof(float), cudaMemcpyDeviceToDevice);

    setup_kernel<<<NBs, Cc>>>(grid_t, phase, t_W1, t_b1, t_W2, t_b2, in_b);

    for (int s = 0; s < NBs; s++){
        const float* x = out + (size_t)s*Bp*Dd;
        float* xn      = out + (size_t)(s+1)*Bp*Dd;

        // score network
        gemm_kernel<<<dim3(Cc/64, Bp/64), 256>>>(x, in_W, nullptr, g_hA, Bp, Cc, Dd, 1, s);
        gemm_kernel<<<dim3(Cc/64, Bp/64), 256>>>(g_hA, h_W + 0*Cc*Cc, h_b + 0*Cc, g_hB, Bp, Cc, Cc, 1, -1);
        gemm_kernel<<<dim3(Cc/64, Bp/64), 256>>>(g_hB, h_W + 1*Cc*Cc, h_b + 1*Cc, g_hA, Bp, Cc, Cc, 1, -1);
        gemm_kernel<<<dim3(Cc/64, Bp/64), 256>>>(g_hA, h_W + 2*Cc*Cc, h_b + 2*Cc, g_hB, Bp, Cc, Cc, 1, -1);
        gemm_kernel<<<dim3(Dd/64, Bp/64), 256>>>(g_hB, out_W, out_b, g_score, Bp, Dd, Cc, 0, -1);

        // repulsion prerequisites
        pairwise_kernel<<<dim3(Bp/64, Bp/64), 256>>>(x);
        median_kernel<<<1, 1024>>>();

        // fused Langevin update
        update_kernel<<<Bp, Dd>>>(x, noises, means, eps, s, xn);
    }
}

// round 3
// speedup vs baseline: 3.3238x; 3.3238x over previous
#include <cuda_runtime.h>
#include <math.h>

#define GRID 128
#define TPB  128
#define Bp   512
#define Dd   64
#define Cc   512
#define NBs  8
#define MC   8
#define NBINS 32768
#define BIN_SC ((float)NBINS/64.0f)

__device__ float g_hA[Bp*Cc];
__device__ float g_hB[Bp*Cc];
__device__ float g_sp[8*Bp*Dd];       // split-K partials of final layer
__device__ float g_d2[Bp*Bp];
__device__ float g_temb[NBs*2*Cc];
__device__ float g_tg1[NBs*Cc];
__device__ float g_bias1[NBs*Cc];
__device__ float g_betas[NBs+1];
__device__ float g_ht;
__device__ int   g_hist[NBINS];
__device__ unsigned long long g_bar = 0ULL;

struct SmG { float A[2][32*32]; float W[2][32*64]; };   // 24KB
struct SmP { float Xi[64*32]; float Xj[64*64]; };       // 24KB
struct SmU { float w[2][512]; float compm[2][MC]; float wm[2][MC]; };
struct SmM { int cnt[TPB]; };
union Smem { SmG g; SmP p; SmU u; SmM m; };

__device__ __forceinline__ float gelu_t(float x){
    float x3 = x*x*x;
    return 0.5f*x*(1.0f+tanhf(0.7978845608028654f*(x+0.044715f*x3)));
}

// software grid barrier: release fence -> arrive -> spin -> acquire fence (CCTL.IVALL)
__device__ __forceinline__ void gridbar(){
    __threadfence();
    __syncthreads();
    if (threadIdx.x == 0){
        unsigned long long old = atomicAdd(&g_bar, 1ULL);
        unsigned long long target = (old/GRID + 1ULL)*GRID;
        while (*(volatile unsigned long long*)&g_bar < target) { }
    }
    __syncthreads();
    __threadfence();
}

// one 32x64 output tile of C = act(A@W + bias); K range [kbeg, kbeg+klen), klen % 32 == 0
__device__ __forceinline__ void gemm_tile(
    const float* __restrict__ A, int Astr, const float* __restrict__ W, int Wstr,
    int m0, int n0, int kbeg, int klen,
    const float* __restrict__ bias, int act, float* __restrict__ C, int Cstr, Smem* sm)
{
    int tid = threadIdx.x;
    int ar = tid>>2, ak = (tid&3)*4;
    int ty = tid>>4, tx = tid&15;
    float acc[4][4] = {};
    int NCk = klen >> 5;

    float4 ra0, ra1, rw[4];
    // prologue: load chunk 0
    ra0 = *(const float4*)&A[(size_t)(m0+ar)*Astr + kbeg + ak];
    ra1 = *(const float4*)&A[(size_t)(m0+ar)*Astr + kbeg + 16 + ak];
    #pragma unroll
    for (int q = 0; q < 4; q++){
        int idx = tid + 128*q;
        int kr = idx>>4, c4 = (idx&15)*4;
        rw[q] = *(const float4*)&W[(size_t)(kbeg+kr)*Wstr + n0 + c4];
    }
    {
        float* As = sm->g.A[0];
        As[(ak+0)*32+ar]=ra0.x; As[(ak+1)*32+ar]=ra0.y; As[(ak+2)*32+ar]=ra0.z; As[(ak+3)*32+ar]=ra0.w;
        As[(16+ak+0)*32+ar]=ra1.x; As[(16+ak+1)*32+ar]=ra1.y; As[(16+ak+2)*32+ar]=ra1.z; As[(16+ak+3)*32+ar]=ra1.w;
        #pragma unroll
        for (int q = 0; q < 4; q++){
            int idx = tid + 128*q;
            int kr = idx>>4, c4 = (idx&15)*4;
            *(float4*)&sm->g.W[0][kr*64 + c4] = rw[q];
        }
    }
    for (int c = 0; c < NCk; c++){
        __syncthreads();
        int cb = c & 1;
        if (c+1 < NCk){
            int kb = kbeg + (c+1)*32;
            ra0 = *(const float4*)&A[(size_t)(m0+ar)*Astr + kb + ak];
            ra1 = *(const float4*)&A[(size_t)(m0+ar)*Astr + kb + 16 + ak];
            #pragma unroll
            for (int q = 0; q < 4; q++){
                int idx = tid + 128*q;
                int kr = idx>>4, c4 = (idx&15)*4;
                rw[q] = *(const float4*)&W[(size_t)(kb+kr)*Wstr + n0 + c4];
            }
        }
        const float* As = sm->g.A[cb];
        const float* Ws = sm->g.W[cb];
        #pragma unroll
        for (int kk = 0; kk < 32; kk++){
            float4 a = *(const float4*)&As[kk*32 + ty*4];
            float4 b = *(const float4*)&Ws[kk*64 + tx*4];
            acc[0][0]+=a.x*b.x; acc[0][1]+=a.x*b.y; acc[0][2]+=a.x*b.z; acc[0][3]+=a.x*b.w;
            acc[1][0]+=a.y*b.x; acc[1][1]+=a.y*b.y; acc[1][2]+=a.y*b.z; acc[1][3]+=a.y*b.w;
            acc[2][0]+=a.z*b.x; acc[2][1]+=a.z*b.y; acc[2][2]+=a.z*b.z; acc[2][3]+=a.z*b.w;
            acc[3][0]+=a.w*b.x; acc[3][1]+=a.w*b.y; acc[3][2]+=a.w*b.z; acc[3][3]+=a.w*b.w;
        }
        if (c+1 < NCk){
            int nb = cb ^ 1;
            float* As2 = sm->g.A[nb];
            As2[(ak+0)*32+ar]=ra0.x; As2[(ak+1)*32+ar]=ra0.y; As2[(ak+2)*32+ar]=ra0.z; As2[(ak+3)*32+ar]=ra0.w;
            As2[(16+ak+0)*32+ar]=ra1.x; As2[(16+ak+1)*32+ar]=ra1.y; As2[(16+ak+2)*32+ar]=ra1.z; As2[(16+ak+3)*32+ar]=ra1.w;
            #pragma unroll
            for (int q = 0; q < 4; q++){
                int idx = tid + 128*q;
                int kr = idx>>4, c4 = (idx&15)*4;
                *(float4*)&sm->g.W[nb][kr*64 + c4] = rw[q];
            }
        }
    }
    #pragma unroll
    for (int i = 0; i < 4; i++){
        int row = m0 + ty*4 + i;
        #pragma unroll
        for (int j = 0; j < 4; j++){
            int col = n0 + tx*4 + j;
            float v = acc[i][j];
            if (bias) v += bias[col];
            if (act)  v = gelu_t(v);
            C[(size_t)row*Cstr + col] = v;
        }
    }
    __syncthreads();
}

// 32x64 tile of pairwise squared distances + histogram
__device__ __forceinline__ void pairwise_tile(const float* __restrict__ x, int i0, int j0, Smem* sm){
    int tid = threadIdx.x;
    {
        int r = tid>>2, kq = (tid&3)*4;
        #pragma unroll
        for (int h = 0; h < 4; h++){
            int k = kq + h*16;
            float4 v = *(const float4*)&x[(i0+r)*Dd + k];
            sm->p.Xi[(k+0)*32+r]=v.x; sm->p.Xi[(k+1)*32+r]=v.y;
            sm->p.Xi[(k+2)*32+r]=v.z; sm->p.Xi[(k+3)*32+r]=v.w;
        }
        #pragma unroll
        for (int q = 0; q < 8; q++){
            int idx = tid + 128*q;
            int row = idx>>4, c4 = (idx&15)*4;
            float4 v = *(const float4*)&x[(j0+row)*Dd + c4];
            sm->p.Xj[(c4+0)*64+row]=v.x; sm->p.Xj[(c4+1)*64+row]=v.y;
            sm->p.Xj[(c4+2)*64+row]=v.z; sm->p.Xj[(c4+3)*64+row]=v.w;
        }
    }
    __syncthreads();
    int ty = tid>>4, tx = tid&15;
    float acc[4][4] = {};
    #pragma unroll
    for (int k = 0; k < 64; k++){
        float4 a = *(const float4*)&sm->p.Xi[k*32 + ty*4];
        float4 b = *(const float4*)&sm->p.Xj[k*64 + tx*4];
        float d;
        d=a.x-b.x; acc[0][0]+=d*d;  d=a.x-b.y; acc[0][1]+=d*d;
        d=a.x-b.z; acc[0][2]+=d*d;  d=a.x-b.w; acc[0][3]+=d*d;
        d=a.y-b.x; acc[1][0]+=d*d;  d=a.y-b.y; acc[1][1]+=d*d;
        d=a.y-b.z; acc[1][2]+=d*d;  d=a.y-b.w; acc[1][3]+=d*d;
        d=a.z-b.x; acc[2][0]+=d*d;  d=a.z-b.y; acc[2][1]+=d*d;
        d=a.z-b.z; acc[2][2]+=d*d;  d=a.z-b.w; acc[2][3]+=d*d;
        d=a.w-b.x; acc[3][0]+=d*d;  d=a.w-b.y; acc[3][1]+=d*d;
        d=a.w-b.z; acc[3][2]+=d*d;  d=a.w-b.w; acc[3][3]+=d*d;
    }
    #pragma unroll
    for (int i = 0; i < 4; i++){
        int gi = i0 + ty*4 + i;
        #pragma unroll
        for (int j = 0; j < 4; j++){
            int gj = j0 + tx*4 + j;
            float d2 = acc[i][j];
            g_d2[gi*Bp + gj] = d2;
            float dist = sqrtf(d2 > 0.f ? d2 : 1e-12f);
            int bin = (int)(dist*BIN_SC);
            if (bin > NBINS-1) bin = NBINS-1;
            atomicAdd(&g_hist[bin], 1);
        }
    }
    __syncthreads();
}

__device__ __forceinline__ void median_sel(Smem* sm){
    int tid = threadIdx.x;
    int base = tid*(NBINS/TPB);
    int ssum = 0;
    for (int b = 0; b < NBINS/TPB; b++) ssum += g_hist[base+b];
    sm->m.cnt[tid] = ssum;
    __syncthreads();
    if (tid == 0){
        long long ks[2] = {(long long)Bp*Bp/2, (long long)Bp*Bp/2 + 1};
        float v[2];
        for (int q = 0; q < 2; q++){
            long long cum = 0; int ch = 0;
            while (ch < TPB && cum + sm->m.cnt[ch] < ks[q]){ cum += sm->m.cnt[ch]; ch++; }
            int bin = ch*(NBINS/TPB), lim = bin + (NBINS/TPB);
            while (bin < lim){ cum += g_hist[bin]; if (cum >= ks[q]) break; bin++; }
            v[q] = ((float)bin + 0.5f) / BIN_SC;
        }
        float med = 0.5f*(v[0]+v[1]);
        g_ht = med*med / logf((float)Bp);
    }
    __syncthreads();
}

__global__ void __launch_bounds__(TPB)
cmcd_fused(const float* __restrict__ particles, const float* __restrict__ noises,
           const float* __restrict__ grid_t, const float* __restrict__ eps,
           const float* __restrict__ means, const float* __restrict__ phase,
           const float* __restrict__ in_W, const float* __restrict__ in_b,
           const float* __restrict__ t_W1, const float* __restrict__ t_b1,
           const float* __restrict__ t_W2, const float* __restrict__ t_b2,
           const float* __restrict__ h_W, const float* __restrict__ h_b,
           const float* __restrict__ out_W, const float* __restrict__ out_b,
           float* __restrict__ out)
{
    __shared__ Smem sm;
    int blk = blockIdx.x, tid = threadIdx.x;
    int gtid = blk*TPB + tid;

    // ── S0: copy slice 0, zero hist, temb (sin/cos), betas ──
    for (int idx = gtid; idx < Bp*Dd; idx += GRID*TPB) out[idx] = particles[idx];
    for (int idx = gtid; idx < NBINS; idx += GRID*TPB) g_hist[idx] = 0;
    for (int idx = gtid; idx < NBs*2*Cc; idx += GRID*TPB){
        int s = idx >> 10, c = idx & 1023;
        float t = (float)s;
        int cc = (c < Cc) ? c : c - Cc;
        float coeff = 0.1f + (float)cc*(99.9f/511.0f);
        float e = coeff*t + phase[cc];
        g_temb[idx] = (c < Cc) ? sinf(e) : cosf(e);
    }
    if (gtid == 0){
        float cum = 0.f;
        g_betas[0] = 0.f;
        for (int j = 0; j < NBs; j++){
            float sg = 1.f/(1.f+expf(-grid_t[j]));
            cum += sg;
            g_betas[j+1] = cum;
        }
        float inv = 1.f/cum;
        for (int j = 1; j <= NBs; j++) g_betas[j] *= inv;
    }
    gridbar();

    // ── S1: t-MLP layer 1 ──
    if (gtid < NBs*Cc){
        int s = gtid >> 9, c = gtid & 511;
        float acc = t_b1[c];
        const float* tb = g_temb + s*2*Cc;
        #pragma unroll 4
        for (int k = 0; k < 2*Cc; k++) acc += tb[k]*t_W1[k*Cc + c];
        g_tg1[gtid] = gelu_t(acc);
    }
    gridbar();

    // ── S2: t-MLP layer 2 + in_b → fused input bias ──
    if (gtid < NBs*Cc){
        int s = gtid >> 9, c = gtid & 511;
        float acc = t_b2[c];
        const float* gb = g_tg1 + s*Cc;
        #pragma unroll 4
        for (int k = 0; k < Cc; k++) acc += gb[k]*t_W2[k*Cc + c];
        g_bias1[gtid] = acc + in_b[c];
    }
    gridbar();

    for (int s = 0; s < NBs; s++){
        const float* x = out + (size_t)s*Bp*Dd;
        float* xn      = out + (size_t)(s+1)*Bp*Dd;

        // ── P1: input layer (K=64) + pairwise d2/hist ──
        {
            int m0 = (blk>>3)*32, n0 = (blk&7)*64;
            gemm_tile(x, Dd, in_W, Cc, m0, n0, 0, Dd, g_bias1 + s*Cc, 1, g_hA, Cc, &sm);
            int i0 = (blk>>3)*32, j0 = (blk&7)*64;
            pairwise_tile(x, i0, j0, &sm);
        }
        gridbar();

        // ── P2-P4: hidden layers ──
        {
            int m0 = (blk>>3)*32, n0 = (blk&7)*64;
            gemm_tile(g_hA, Cc, h_W + 0*Cc*Cc, Cc, m0, n0, 0, Cc, h_b + 0*Cc, 1, g_hB, Cc, &sm);
            gridbar();
            gemm_tile(g_hB, Cc, h_W + 1*Cc*Cc, Cc, m0, n0, 0, Cc, h_b + 1*Cc, 1, g_hA, Cc, &sm);
            gridbar();
            gemm_tile(g_hA, Cc, h_W + 2*Cc*Cc, Cc, m0, n0, 0, Cc, h_b + 2*Cc, 1, g_hB, Cc, &sm);
            gridbar();
        }

        // ── P5: output layer split-K partials (+ median on block 0) ──
        {
            int mt = blk & 15, ks = blk >> 4;
            gemm_tile(g_hB, Cc, out_W, Dd, mt*32, 0, ks*64, 64, nullptr, 0,
                      g_sp + (size_t)ks*Bp*Dd, Dd, &sm);
            if (blk == 0) median_sel(&sm);
        }
        gridbar();

        // ── P6: fused Langevin update + hist re-zero ──
        {
            int half = tid >> 6;
            int d = tid & 63;
            float dt = eps[0];
            float t = g_betas[s];
            float inv_ht = 1.f/g_ht;
            float s2dt = sqrtf(2.f*dt);
            for (int p = 0; p < 2; p++){
                int i = blk*4 + p*2 + half;
                float xi_d = x[i*Dd + d];
                #pragma unroll
                for (int q = 0; q < 8; q++){
                    int j = d + q*64;
                    sm.u.w[half][j] = expf(-g_d2[i*Bp + j]*inv_ht);
                }
                if (d < MC){
                    float sacc = 0.f;
                    #pragma unroll 4
                    for (int k = 0; k < Dd; k++){
                        float df = x[i*Dd + k] - means[d*Dd + k];
                        sacc += df*df;
                    }
                    sm.u.compm[half][d] = -0.5f*sacc;
                }
                __syncthreads();
                if (d == 0){
                    float mx = sm.u.compm[half][0];
                    for (int m = 1; m < MC; m++) mx = fmaxf(mx, sm.u.compm[half][m]);
                    float se = 0.f;
                    for (int m = 0; m < MC; m++){
                        float e = expf(sm.u.compm[half][m]-mx);
                        sm.u.wm[half][m] = e; se += e;
                    }
                    float inv = 1.f/se;
                    for (int m = 0; m < MC; m++) sm.u.wm[half][m] *= inv;
                }
                __syncthreads();
                float wbar = 0.f;
                #pragma unroll
                for (int m = 0; m < MC; m++) wbar += sm.u.wm[half][m]*means[m*Dd + d];
                float r = 0.f;
                const float* wrow = sm.u.w[half];
                #pragma unroll 8
                for (int j = 0; j < Bp; j++)
                    r += wrow[j]*(xi_d - x[j*Dd + d]);
                float score = out_b[d];
                #pragma unroll
                for (int ks = 0; ks < 8; ks++) score += g_sp[(size_t)ks*Bp*Dd + i*Dd + d];
                float drift = t*wbar - xi_d - score;
                float nv = noises[((size_t)s*Bp + i)*Dd + d];
                xn[i*Dd + d] = xi_d + dt*drift + s2dt*nv + 0.1f*dt*inv_ht*r;
                __syncthreads();
            }
            for (int idx = gtid; idx < NBINS; idx += GRID*TPB) g_hist[idx] = 0;
        }
        gridbar();
    }
}

extern "C" void kernel_launch(void* const* d_in, const int* in_sizes, int n_in,
                              void* d_out, int out_size){
    const float* particles = (const float*)d_in[0];
    const float* noises    = (const float*)d_in[1];
    const float* grid_t    = (const float*)d_in[2];
    const float* eps       = (const float*)d_in[3];
    const float* means     = (const float*)d_in[4];
    const float* phase     = (const float*)d_in[5];
    const float* in_W      = (const float*)d_in[6];
    const float* in_b      = (const float*)d_in[7];
    const float* t_W1      = (const float*)d_in[8];
    const float* t_b1      = (const float*)d_in[9];
    const float* t_W2      = (const float*)d_in[10];
    const float* t_b2      = (const float*)d_in[11];
    const float* h_W       = (const float*)d_in[12];
    const float* h_b       = (const float*)d_in[13];
    const float* out_W     = (const float*)d_in[14];
    const float* out_b     = (const float*)d_in[15];
    float* out = (float*)d_out;

    cmcd_fused<<<GRID, TPB>>>(particles, noises, grid_t, eps, means, phase,
                              in_W, in_b, t_W1, t_b1, t_W2, t_b2,
                              h_W, h_b, out_W, out_b, out);
}

// round 5
// speedup vs baseline: 3.9369x; 1.1845x over previous
#include <cuda_runtime.h>
#include <math.h>

#define GRID 128
#define TPB  128
#define Bp   512
#define Dd   64
#define Cc   512
#define NBs  8
#define MC   8
#define NBINS 32768
#define BIN_SC ((float)NBINS/64.0f)

__device__ float g_hA[Bp*Cc];
__device__ float g_hB[Bp*Cc];
__device__ float g_sp[8*Bp*Dd];       // split-K partials of final layer
__device__ float g_d2[Bp*Bp];
__device__ float g_temb[NBs*2*Cc];
__device__ float g_tg1[NBs*Cc];
__device__ float g_bias1[NBs*Cc];
__device__ float g_betas[NBs+1];
__device__ float g_ht;
__device__ int   g_hist[NBINS];
__device__ unsigned long long g_bar = 0ULL;

#define ASTR 36   // A smem row stride (floats): conflict-free frag loads
#define WSTR 40   // W smem row stride

struct SmG { float A[2][64*ASTR]; float W[2][32*WSTR]; };  // 28672 B
struct SmP { float Xi[64*32]; float Xj[64*64]; };          // 24576 B
struct SmU { float w[2][512]; float compm[2][MC]; float wm[2][MC]; };
struct SmM { int cnt[TPB]; };
union Smem { SmG g; SmP p; SmU u; SmM m; };

__device__ __forceinline__ float gelu_t(float x){
    float x3 = x*x*x;
    return 0.5f*x*(1.0f+tanhf(0.7978845608028654f*(x+0.044715f*x3)));
}

__device__ __forceinline__ unsigned f2tf(float x){
    unsigned u;
    asm("cvt.rna.tf32.f32 %0, %1;" : "=r"(u) : "f"(x));
    return u;
}

__device__ __forceinline__ void mma_tf32(float* acc,
    unsigned a0, unsigned a1, unsigned a2, unsigned a3,
    unsigned b0, unsigned b1)
{
    asm volatile(
        "mma.sync.aligned.m16n8k8.row.col.f32.tf32.tf32.f32 "
        "{%0,%1,%2,%3}, {%4,%5,%6,%7}, {%8,%9}, {%0,%1,%2,%3};"
        : "+f"(acc[0]), "+f"(acc[1]), "+f"(acc[2]), "+f"(acc[3])
        : "r"(a0), "r"(a1), "r"(a2), "r"(a3), "r"(b0), "r"(b1));
}

// software grid barrier (monotone counter; safe across graph replays)
__device__ __forceinline__ void gridbar(){
    __threadfence();
    __syncthreads();
    if (threadIdx.x == 0){
        unsigned long long old = atomicAdd(&g_bar, 1ULL);
        unsigned long long target = (old/GRID + 1ULL)*GRID;
        while (*(volatile unsigned long long*)&g_bar < target) { }
    }
    __syncthreads();
    __threadfence();
}

// one 64x32 output tile of C = act(A@W + bias) via tf32 tensor cores.
// K range [kbeg, kbeg+klen), klen % 32 == 0. 128 threads (4 warps x 16 rows).
__device__ __forceinline__ void gemm_tile_tc(
    const float* __restrict__ A, int Astr, const float* __restrict__ W, int Wstr,
    int m0, int n0, int kbeg, int klen,
    const float* __restrict__ bias, int act, float* __restrict__ C, int Cstr, Smem* sm)
{
    int tid  = threadIdx.x;
    int warp = tid >> 5, lane = tid & 31;
    int g = lane >> 2, t = lane & 3;

    // gmem->smem staging roles
    int arow = tid >> 1;           // 0..63
    int kseg = (tid & 1) * 16;     // 0 or 16
    int wk   = tid >> 2;           // 0..31
    int nseg = (tid & 3) * 8;      // 0,8,16,24

    float acc[4][4] = {};
    int NC = klen >> 5;

    float4 ra[4], rw[2];
    // prologue: chunk 0
    #pragma unroll
    for (int q = 0; q < 4; q++)
        ra[q] = *(const float4*)&A[(size_t)(m0+arow)*Astr + kbeg + kseg + 4*q];
    #pragma unroll
    for (int q = 0; q < 2; q++)
        rw[q] = *(const float4*)&W[(size_t)(kbeg+wk)*Wstr + n0 + nseg + 4*q];
    {
        float* As = sm->g.A[0]; float* Ws = sm->g.W[0];
        #pragma unroll
        for (int q = 0; q < 4; q++) *(float4*)&As[arow*ASTR + kseg + 4*q] = ra[q];
        #pragma unroll
        for (int q = 0; q < 2; q++) *(float4*)&Ws[wk*WSTR + nseg + 4*q] = rw[q];
    }

    for (int c = 0; c < NC; c++){
        __syncthreads();
        int cb = c & 1;
        if (c+1 < NC){
            int kb = kbeg + (c+1)*32;
            #pragma unroll
            for (int q = 0; q < 4; q++)
                ra[q] = *(const float4*)&A[(size_t)(m0+arow)*Astr + kb + kseg + 4*q];
            #pragma unroll
            for (int q = 0; q < 2; q++)
                rw[q] = *(const float4*)&W[(size_t)(kb+wk)*Wstr + n0 + nseg + 4*q];
        }
        const float* As = sm->g.A[cb];
        const float* Ws = sm->g.W[cb];
        #pragma unroll
        for (int kk = 0; kk < 4; kk++){
            int ab = (16*warp + g)*ASTR + kk*8;
            unsigned a0 = f2tf(As[ab + t]);
            unsigned a1 = f2tf(As[ab + 8*ASTR + t]);
            unsigned a2 = f2tf(As[ab + t + 4]);
            unsigned a3 = f2tf(As[ab + 8*ASTR + t + 4]);
            #pragma unroll
            for (int c4 = 0; c4 < 4; c4++){
                unsigned b0 = f2tf(Ws[(kk*8 + t)*WSTR + c4*8 + g]);
                unsigned b1 = f2tf(Ws[(kk*8 + t + 4)*WSTR + c4*8 + g]);
                mma_tf32(acc[c4], a0, a1, a2, a3, b0, b1);
            }
        }
        if (c+1 < NC){
            int nb = cb ^ 1;
            float* As2 = sm->g.A[nb]; float* Ws2 = sm->g.W[nb];
            #pragma unroll
            for (int q = 0; q < 4; q++) *(float4*)&As2[arow*ASTR + kseg + 4*q] = ra[q];
            #pragma unroll
            for (int q = 0; q < 2; q++) *(float4*)&Ws2[wk*WSTR + nseg + 4*q] = rw[q];
        }
    }

    int r0 = m0 + 16*warp + g;
    #pragma unroll
    for (int c4 = 0; c4 < 4; c4++){
        int n = n0 + c4*8 + 2*t;
        float v00 = acc[c4][0], v01 = acc[c4][1];
        float v10 = acc[c4][2], v11 = acc[c4][3];
        if (bias){ v00 += bias[n]; v01 += bias[n+1]; v10 += bias[n]; v11 += bias[n+1]; }
        if (act){ v00 = gelu_t(v00); v01 = gelu_t(v01); v10 = gelu_t(v10); v11 = gelu_t(v11); }
        C[(size_t)r0*Cstr + n]       = v00;
        C[(size_t)r0*Cstr + n + 1]   = v01;
        C[(size_t)(r0+8)*Cstr + n]   = v10;
        C[(size_t)(r0+8)*Cstr + n+1] = v11;
    }
    __syncthreads();
}

// 32x64 tile of pairwise squared distances + histogram
__device__ __forceinline__ void pairwise_tile(const float* __restrict__ x, int i0, int j0, Smem* sm){
    int tid = threadIdx.x;
    {
        int r = tid>>2, kq = (tid&3)*4;
        #pragma unroll
        for (int h = 0; h < 4; h++){
            int k = kq + h*16;
            float4 v = *(const float4*)&x[(i0+r)*Dd + k];
            sm->p.Xi[(k+0)*32+r]=v.x; sm->p.Xi[(k+1)*32+r]=v.y;
            sm->p.Xi[(k+2)*32+r]=v.z; sm->p.Xi[(k+3)*32+r]=v.w;
        }
        #pragma unroll
        for (int q = 0; q < 8; q++){
            int idx = tid + 128*q;
            int row = idx>>4, c4 = (idx&15)*4;
            float4 v = *(const float4*)&x[(j0+row)*Dd + c4];
            sm->p.Xj[(c4+0)*64+row]=v.x; sm->p.Xj[(c4+1)*64+row]=v.y;
            sm->p.Xj[(c4+2)*64+row]=v.z; sm->p.Xj[(c4+3)*64+row]=v.w;
        }
    }
    __syncthreads();
    int ty = tid>>4, tx = tid&15;
    float acc[4][4] = {};
    #pragma unroll
    for (int k = 0; k < 64; k++){
        float4 a = *(const float4*)&sm->p.Xi[k*32 + ty*4];
        float4 b = *(const float4*)&sm->p.Xj[k*64 + tx*4];
        float d;
        d=a.x-b.x; acc[0][0]+=d*d;  d=a.x-b.y; acc[0][1]+=d*d;
        d=a.x-b.z; acc[0][2]+=d*d;  d=a.x-b.w; acc[0][3]+=d*d;
        d=a.y-b.x; acc[1][0]+=d*d;  d=a.y-b.y; acc[1][1]+=d*d;
        d=a.y-b.z; acc[1][2]+=d*d;  d=a.y-b.w; acc[1][3]+=d*d;
        d=a.z-b.x; acc[2][0]+=d*d;  d=a.z-b.y; acc[2][1]+=d*d;
        d=a.z-b.z; acc[2][2]+=d*d;  d=a.z-b.w; acc[2][3]+=d*d;
        d=a.w-b.x; acc[3][0]+=d*d;  d=a.w-b.y; acc[3][1]+=d*d;
        d=a.w-b.z; acc[3][2]+=d*d;  d=a.w-b.w; acc[3][3]+=d*d;
    }
    #pragma unroll
    for (int i = 0; i < 4; i++){
        int gi = i0 + ty*4 + i;
        #pragma unroll
        for (int j = 0; j < 4; j++){
            int gj = j0 + tx*4 + j;
            float d2 = acc[i][j];
            g_d2[gi*Bp + gj] = d2;
            float dist = sqrtf(d2 > 0.f ? d2 : 1e-12f);
            int bin = (int)(dist*BIN_SC);
            if (bin > NBINS-1) bin = NBINS-1;
            atomicAdd(&g_hist[bin], 1);
        }
    }
    __syncthreads();
}

__device__ __forceinline__ void median_sel(Smem* sm){
    int tid = threadIdx.x;
    int base = tid*(NBINS/TPB);
    int ssum = 0;
    for (int b = 0; b < NBINS/TPB; b++) ssum += g_hist[base+b];
    sm->m.cnt[tid] = ssum;
    __syncthreads();
    if (tid == 0){
        long long ks[2] = {(long long)Bp*Bp/2, (long long)Bp*Bp/2 + 1};
        float v[2];
        for (int q = 0; q < 2; q++){
            long long cum = 0; int ch = 0;
            while (ch < TPB && cum + sm->m.cnt[ch] < ks[q]){ cum += sm->m.cnt[ch]; ch++; }
            int bin = ch*(NBINS/TPB), lim = bin + (NBINS/TPB);
            while (bin < lim){ cum += g_hist[bin]; if (cum >= ks[q]) break; bin++; }
            v[q] = ((float)bin + 0.5f) / BIN_SC;
        }
        float med = 0.5f*(v[0]+v[1]);
        g_ht = med*med / logf((float)Bp);
    }
    __syncthreads();
}

__global__ void __launch_bounds__(TPB, 1)
cmcd_fused(const float* __restrict__ particles, const float* __restrict__ noises,
           const float* __restrict__ grid_t, const float* __restrict__ eps,
           const float* __restrict__ means, const float* __restrict__ phase,
           const float* __restrict__ in_W, const float* __restrict__ in_b,
           const float* __restrict__ t_W1, const float* __restrict__ t_b1,
           const float* __restrict__ t_W2, const float* __restrict__ t_b2,
           const float* __restrict__ h_W, const float* __restrict__ h_b,
           const float* __restrict__ out_W, const float* __restrict__ out_b,
           float* __restrict__ out)
{
    __shared__ Smem sm;
    int blk = blockIdx.x, tid = threadIdx.x;
    int gtid = blk*TPB + tid;

    // ── S0: copy slice 0, zero hist, temb (sin/cos), betas ──
    for (int idx = gtid; idx < Bp*Dd; idx += GRID*TPB) out[idx] = particles[idx];
    for (int idx = gtid; idx < NBINS; idx += GRID*TPB) g_hist[idx] = 0;
    for (int idx = gtid; idx < NBs*2*Cc; idx += GRID*TPB){
        int s = idx >> 10, c = idx & 1023;
        float t = (float)s;
        int cc = (c < Cc) ? c : c - Cc;
        float coeff = 0.1f + (float)cc*(99.9f/511.0f);
        float e = coeff*t + phase[cc];
        g_temb[idx] = (c < Cc) ? sinf(e) : cosf(e);
    }
    if (gtid == 0){
        float cum = 0.f;
        g_betas[0] = 0.f;
        for (int j = 0; j < NBs; j++){
            float sg = 1.f/(1.f+expf(-grid_t[j]));
            cum += sg;
            g_betas[j+1] = cum;
        }
        float inv = 1.f/cum;
        for (int j = 1; j <= NBs; j++) g_betas[j] *= inv;
    }
    gridbar();

    // ── S1: t-MLP layer 1 ──
    if (gtid < NBs*Cc){
        int s = gtid >> 9, c = gtid & 511;
        float acc = t_b1[c];
        const float* tb = g_temb + s*2*Cc;
        #pragma unroll 4
        for (int k = 0; k < 2*Cc; k++) acc += tb[k]*t_W1[k*Cc + c];
        g_tg1[gtid] = gelu_t(acc);
    }
    gridbar();

    // ── S2: t-MLP layer 2 + in_b → fused input bias ──
    if (gtid < NBs*Cc){
        int s = gtid >> 9, c = gtid & 511;
        float acc = t_b2[c];
        const float* gb = g_tg1 + s*Cc;
        #pragma unroll 4
        for (int k = 0; k < Cc; k++) acc += gb[k]*t_W2[k*Cc + c];
        g_bias1[gtid] = acc + in_b[c];
    }
    gridbar();

    int m0 = (blk >> 4) * 64;     // 8 m-tiles of 64 rows
    int n0 = (blk & 15) * 32;     // 16 n-tiles of 32 cols

    for (int s = 0; s < NBs; s++){
        const float* x = out + (size_t)s*Bp*Dd;
        float* xn      = out + (size_t)(s+1)*Bp*Dd;

        // ── P1: input layer (K=64) + pairwise d2/hist ──
        gemm_tile_tc(x, Dd, in_W, Cc, m0, n0, 0, Dd, g_bias1 + s*Cc, 1, g_hA, Cc, &sm);
        pairwise_tile(x, (blk>>3)*32, (blk&7)*64, &sm);
        gridbar();

        // ── P2-P4: hidden layers ──
        gemm_tile_tc(g_hA, Cc, h_W + 0*Cc*Cc, Cc, m0, n0, 0, Cc, h_b + 0*Cc, 1, g_hB, Cc, &sm);
        gridbar();
        gemm_tile_tc(g_hB, Cc, h_W + 1*Cc*Cc, Cc, m0, n0, 0, Cc, h_b + 1*Cc, 1, g_hA, Cc, &sm);
        gridbar();
        gemm_tile_tc(g_hA, Cc, h_W + 2*Cc*Cc, Cc, m0, n0, 0, Cc, h_b + 2*Cc, 1, g_hB, Cc, &sm);
        gridbar();

        // ── P5: output layer split-K partials (+ median on block 0) ──
        {
            int ksp = blk >> 4;            // 0..7 k-split
            int rem = blk & 15;
            int om0 = (rem >> 1) * 64;     // 8 m-tiles
            int on0 = (rem & 1) * 32;      // 2 n-tiles
            gemm_tile_tc(g_hB, Cc, out_W, Dd, om0, on0, ksp*64, 64, nullptr, 0,
                         g_sp + (size_t)ksp*Bp*Dd, Dd, &sm);
            if (blk == 0) median_sel(&sm);
        }
        gridbar();

        // ── P6: fused Langevin update + hist re-zero ──
        {
            int half = tid >> 6;
            int d = tid & 63;
            float dt = eps[0];
            float t = g_betas[s];
            float inv_ht = 1.f/g_ht;
            float s2dt = sqrtf(2.f*dt);
            for (int p = 0; p < 2; p++){
                int i = blk*4 + p*2 + half;
                float xi_d = x[i*Dd + d];
                #pragma unroll
                for (int q = 0; q < 8; q++){
                    int j = d + q*64;
                    sm.u.w[half][j] = expf(-g_d2[i*Bp + j]*inv_ht);
                }
                if (d < MC){
                    float sacc = 0.f;
                    #pragma unroll 4
                    for (int k = 0; k < Dd; k++){
                        float df = x[i*Dd + k] - means[d*Dd + k];
                        sacc += df*df;
                    }
                    sm.u.compm[half][d] = -0.5f*sacc;
                }
                __syncthreads();
                if (d == 0){
                    float mx = sm.u.compm[half][0];
                    for (int m = 1; m < MC; m++) mx = fmaxf(mx, sm.u.compm[half][m]);
                    float se = 0.f;
                    for (int m = 0; m < MC; m++){
                        float e = expf(sm.u.compm[half][m]-mx);
                        sm.u.wm[half][m] = e; se += e;
                    }
                    float inv = 1.f/se;
                    for (int m = 0; m < MC; m++) sm.u.wm[half][m] *= inv;
                }
                __syncthreads();
                float wbar = 0.f;
                #pragma unroll
                for (int m = 0; m < MC; m++) wbar += sm.u.wm[half][m]*means[m*Dd + d];
                float r = 0.f;
                const float* wrow = sm.u.w[half];
                #pragma unroll 8
                for (int j = 0; j < Bp; j++)
                    r += wrow[j]*(xi_d - x[j*Dd + d]);
                float score = out_b[d];
                #pragma unroll
                for (int ks = 0; ks < 8; ks++) score += g_sp[(size_t)ks*Bp*Dd + i*Dd + d];
                float drift = t*wbar - xi_d - score;
                float nv = noises[((size_t)s*Bp + i)*Dd + d];
                xn[i*Dd + d] = xi_d + dt*drift + s2dt*nv + 0.1f*dt*inv_ht*r;
                __syncthreads();
            }
            for (int idx = gtid; idx < NBINS; idx += GRID*TPB) g_hist[idx] = 0;
        }
        gridbar();
    }
}

extern "C" void kernel_launch(void* const* d_in, const int* in_sizes, int n_in,
                              void* d_out, int out_size){
    const float* particles = (const float*)d_in[0];
    const float* noises    = (const float*)d_in[1];
    const float* grid_t    = (const float*)d_in[2];
    const float* eps       = (const float*)d_in[3];
    const float* means     = (const float*)d_in[4];
    const float* phase     = (const float*)d_in[5];
    const float* in_W      = (const float*)d_in[6];
    const float* in_b      = (const float*)d_in[7];
    const float* t_W1      = (const float*)d_in[8];
    const float* t_b1      = (const float*)d_in[9];
    const float* t_W2      = (const float*)d_in[10];
    const float* t_b2      = (const float*)d_in[11];
    const float* h_W       = (const float*)d_in[12];
    const float* h_b       = (const float*)d_in[13];
    const float* out_W     = (const float*)d_in[14];
    const float* out_b     = (const float*)d_in[15];
    float* out = (float*)d_out;

    cmcd_fused<<<GRID, TPB>>>(particles, noises, grid_t, eps, means, phase,
                              in_W, in_b, t_W1, t_b1, t_W2, t_b2,
                              h_W, h_b, out_W, out_b, out);
}

// round 6
// speedup vs baseline: 5.5901x; 1.4199x over previous
#include <cuda_runtime.h>
#include <math.h>

#define GRID 128
#define TPB  256
#define Bp   512
#define Dd   64
#define Cc   512
#define NBs  8
#define MC   8
#define NBINS 32768
#define BIN_SC ((float)NBINS/64.0f)

__device__ float g_hA[Bp*Cc];
__device__ float g_hB[Bp*Cc];
__device__ float g_sp[8*Bp*Dd];       // split-K partials of final layer
__device__ float g_d2[Bp*Bp];
__device__ float g_temb[NBs*2*Cc];
__device__ float g_tg1[NBs*Cc];
__device__ float g_bias1[NBs*Cc];
__device__ float g_betas[NBs+1];
__device__ int   g_hist[2][NBINS];
__device__ unsigned long long g_bar = 0ULL;

#define ASTR 36   // A smem row stride (floats): conflict-free frag loads
#define WSTR 40   // W smem row stride

struct SmG { float A[2][2][64*ASTR]; float W[2][2][32*WSTR]; float red[64*33]; };
struct SmP { float Xi[64*32]; float Xj[64*64]; };
struct SmU { float w[4][Bp]; float compm[4][MC]; float wm[4][MC]; };
struct SmM { int cnt[TPB]; float v[2]; };
union Smem { SmG g; SmP p; SmU u; SmM m; };

__device__ __forceinline__ float gelu_t(float x){
    float x3 = x*x*x;
    return 0.5f*x*(1.0f+tanhf(0.7978845608028654f*(x+0.044715f*x3)));
}

__device__ __forceinline__ unsigned f2tf(float x){
    unsigned u;
    asm("cvt.rna.tf32.f32 %0, %1;" : "=r"(u) : "f"(x));
    return u;
}

__device__ __forceinline__ void mma_tf32(float* acc,
    unsigned a0, unsigned a1, unsigned a2, unsigned a3,
    unsigned b0, unsigned b1)
{
    asm volatile(
        "mma.sync.aligned.m16n8k8.row.col.f32.tf32.tf32.f32 "
        "{%0,%1,%2,%3}, {%4,%5,%6,%7}, {%8,%9}, {%0,%1,%2,%3};"
        : "+f"(acc[0]), "+f"(acc[1]), "+f"(acc[2]), "+f"(acc[3])
        : "r"(a0), "r"(a1), "r"(a2), "r"(a3), "r"(b0), "r"(b1));
}

// software grid barrier (monotone counter; safe across graph replays)
__device__ __forceinline__ void gridbar(){
    __threadfence();
    __syncthreads();
    if (threadIdx.x == 0){
        unsigned long long old = atomicAdd(&g_bar, 1ULL);
        unsigned long long target = (old/GRID + 1ULL)*GRID;
        while (*(volatile unsigned long long*)&g_bar < target) { }
    }
    __syncthreads();
    __threadfence();
}

// one 64x32 output tile of C = act(A@W + bias) via tf32 tensor cores.
// 256 threads: warp-group 0 (threads 0-127) takes K lower half, group 1 upper
// half; smem reduction, group 0 does the epilogue.
__device__ __forceinline__ void gemm_tile_tc(
    const float* __restrict__ A, int Astr, const float* __restrict__ W, int Wstr,
    int m0, int n0, int kbeg, int klen,
    const float* __restrict__ bias, int act, float* __restrict__ C, int Cstr, Smem* sm)
{
    int tid  = threadIdx.x;
    int gid  = tid >> 7;            // K-split group (0/1)
    int tg   = tid & 127;
    int warp = tg >> 5, lane = tid & 31;
    int g = lane >> 2, t = lane & 3;

    // gmem->smem staging roles (within group)
    int arow = tg >> 1;             // 0..63
    int kseg = (tg & 1) * 16;       // 0 or 16
    int wk   = tg >> 2;             // 0..31
    int nseg = (tg & 3) * 8;        // 0,8,16,24

    int khalf = klen >> 1;
    int kb0   = kbeg + gid*khalf;
    int NC    = khalf >> 5;

    float acc[4][4] = {};

    float4 ra[4], rw[2];
    #pragma unroll
    for (int q = 0; q < 4; q++)
        ra[q] = *(const float4*)&A[(size_t)(m0+arow)*Astr + kb0 + kseg + 4*q];
    #pragma unroll
    for (int q = 0; q < 2; q++)
        rw[q] = *(const float4*)&W[(size_t)(kb0+wk)*Wstr + n0 + nseg + 4*q];
    {
        float* As = sm->g.A[gid][0]; float* Ws = sm->g.W[gid][0];
        #pragma unroll
        for (int q = 0; q < 4; q++) *(float4*)&As[arow*ASTR + kseg + 4*q] = ra[q];
        #pragma unroll
        for (int q = 0; q < 2; q++) *(float4*)&Ws[wk*WSTR + nseg + 4*q] = rw[q];
    }

    for (int c = 0; c < NC; c++){
        __syncthreads();
        int cb = c & 1;
        if (c+1 < NC){
            int kb = kb0 + (c+1)*32;
            #pragma unroll
            for (int q = 0; q < 4; q++)
                ra[q] = *(const float4*)&A[(size_t)(m0+arow)*Astr + kb + kseg + 4*q];
            #pragma unroll
            for (int q = 0; q < 2; q++)
                rw[q] = *(const float4*)&W[(size_t)(kb+wk)*Wstr + n0 + nseg + 4*q];
        }
        const float* As = sm->g.A[gid][cb];
        const float* Ws = sm->g.W[gid][cb];
        #pragma unroll
        for (int kk = 0; kk < 4; kk++){
            int ab = (16*warp + g)*ASTR + kk*8;
            unsigned a0 = f2tf(As[ab + t]);
            unsigned a1 = f2tf(As[ab + 8*ASTR + t]);
            unsigned a2 = f2tf(As[ab + t + 4]);
            unsigned a3 = f2tf(As[ab + 8*ASTR + t + 4]);
            #pragma unroll
            for (int c4 = 0; c4 < 4; c4++){
                unsigned b0 = f2tf(Ws[(kk*8 + t)*WSTR + c4*8 + g]);
                unsigned b1 = f2tf(Ws[(kk*8 + t + 4)*WSTR + c4*8 + g]);
                mma_tf32(acc[c4], a0, a1, a2, a3, b0, b1);
            }
        }
        if (c+1 < NC){
            int nb = cb ^ 1;
            float* As2 = sm->g.A[gid][nb]; float* Ws2 = sm->g.W[gid][nb];
            #pragma unroll
            for (int q = 0; q < 4; q++) *(float4*)&As2[arow*ASTR + kseg + 4*q] = ra[q];
            #pragma unroll
            for (int q = 0; q < 2; q++) *(float4*)&Ws2[wk*WSTR + nseg + 4*q] = rw[q];
        }
    }

    __syncthreads();
    int r0 = 16*warp + g;
    if (gid == 1){
        #pragma unroll
        for (int c4 = 0; c4 < 4; c4++){
            int col = c4*8 + 2*t;
            sm->g.red[r0*33 + col]       = acc[c4][0];
            sm->g.red[r0*33 + col + 1]   = acc[c4][1];
            sm->g.red[(r0+8)*33 + col]   = acc[c4][2];
            sm->g.red[(r0+8)*33 + col+1] = acc[c4][3];
        }
    }
    __syncthreads();
    if (gid == 0){
        #pragma unroll
        for (int c4 = 0; c4 < 4; c4++){
            int col = c4*8 + 2*t;
            float v00 = acc[c4][0] + sm->g.red[r0*33 + col];
            float v01 = acc[c4][1] + sm->g.red[r0*33 + col + 1];
            float v10 = acc[c4][2] + sm->g.red[(r0+8)*33 + col];
            float v11 = acc[c4][3] + sm->g.red[(r0+8)*33 + col+1];
            int n = n0 + col;
            if (bias){ v00 += bias[n]; v01 += bias[n+1]; v10 += bias[n]; v11 += bias[n+1]; }
            if (act){ v00 = gelu_t(v00); v01 = gelu_t(v01); v10 = gelu_t(v10); v11 = gelu_t(v11); }
            C[(size_t)(m0+r0)*Cstr + n]       = v00;
            C[(size_t)(m0+r0)*Cstr + n + 1]   = v01;
            C[(size_t)(m0+r0+8)*Cstr + n]     = v10;
            C[(size_t)(m0+r0+8)*Cstr + n + 1] = v11;
        }
    }
    __syncthreads();
}

// 32x64 tile of pairwise squared distances + histogram (256 threads)
__device__ __forceinline__ void pairwise_tile(const float* __restrict__ x, int i0, int j0,
                                              int* __restrict__ hist, Smem* sm){
    int tid = threadIdx.x;
    #pragma unroll
    for (int q = 0; q < 2; q++){
        int idx = tid + 256*q;
        int r = idx>>4, c4 = (idx&15)*4;
        float4 v = *(const float4*)&x[(i0+r)*Dd + c4];
        sm->p.Xi[(c4+0)*32+r]=v.x; sm->p.Xi[(c4+1)*32+r]=v.y;
        sm->p.Xi[(c4+2)*32+r]=v.z; sm->p.Xi[(c4+3)*32+r]=v.w;
    }
    #pragma unroll
    for (int q = 0; q < 4; q++){
        int idx = tid + 256*q;
        int row = idx>>4, c4 = (idx&15)*4;
        float4 v = *(const float4*)&x[(j0+row)*Dd + c4];
        sm->p.Xj[(c4+0)*64+row]=v.x; sm->p.Xj[(c4+1)*64+row]=v.y;
        sm->p.Xj[(c4+2)*64+row]=v.z; sm->p.Xj[(c4+3)*64+row]=v.w;
    }
    __syncthreads();
    int ty = tid>>4, tx = tid&15;          // 16x16 thread grid, 2x4 micro
    float acc[2][4] = {};
    #pragma unroll
    for (int k = 0; k < 64; k++){
        float a0 = sm->p.Xi[k*32 + ty*2];
        float a1 = sm->p.Xi[k*32 + ty*2 + 1];
        float4 b = *(const float4*)&sm->p.Xj[k*64 + tx*4];
        float d;
        d=a0-b.x; acc[0][0]+=d*d;  d=a0-b.y; acc[0][1]+=d*d;
        d=a0-b.z; acc[0][2]+=d*d;  d=a0-b.w; acc[0][3]+=d*d;
        d=a1-b.x; acc[1][0]+=d*d;  d=a1-b.y; acc[1][1]+=d*d;
        d=a1-b.z; acc[1][2]+=d*d;  d=a1-b.w; acc[1][3]+=d*d;
    }
    #pragma unroll
    for (int i = 0; i < 2; i++){
        int gi = i0 + ty*2 + i;
        #pragma unroll
        for (int j = 0; j < 4; j++){
            int gj = j0 + tx*4 + j;
            float d2 = acc[i][j];
            g_d2[gi*Bp + gj] = d2;
            float dist = sqrtf(d2 > 0.f ? d2 : 1e-12f);
            int bin = (int)(dist*BIN_SC);
            if (bin > NBINS-1) bin = NBINS-1;
            atomicAdd(&hist[bin], 1);
        }
    }
    __syncthreads();
}

// every block computes the exact median locally (prefix scan over chunk counts)
__device__ __forceinline__ float median_local(const int* __restrict__ hist, Smem* sm){
    int tid = threadIdx.x;
    const int per = NBINS/TPB;   // 128
    int ssum = 0;
    #pragma unroll 8
    for (int b = 0; b < per; b++) ssum += hist[tid*per + b];
    sm->m.cnt[tid] = ssum;
    __syncthreads();
    #pragma unroll
    for (int off = 1; off < TPB; off <<= 1){
        int v = (tid >= off) ? sm->m.cnt[tid-off] : 0;
        __syncthreads();
        sm->m.cnt[tid] += v;
        __syncthreads();
    }
    long long k1 = (long long)Bp*Bp/2, k2 = k1 + 1;
    int prev = tid ? sm->m.cnt[tid-1] : 0;
    int cur  = sm->m.cnt[tid];
    if (prev < k1 && k1 <= cur){
        int cum = prev, b = tid*per;
        while (cum + hist[b] < k1){ cum += hist[b]; b++; }
        sm->m.v[0] = ((float)b + 0.5f)/BIN_SC;
    }
    if (prev < k2 && k2 <= cur){
        int cum = prev, b = tid*per;
        while (cum + hist[b] < k2){ cum += hist[b]; b++; }
        sm->m.v[1] = ((float)b + 0.5f)/BIN_SC;
    }
    __syncthreads();
    float med = 0.5f*(sm->m.v[0] + sm->m.v[1]);
    float ht = med*med / logf((float)Bp);
    __syncthreads();     // everyone has read v[] before the union is reused
    return ht;
}

__global__ void __launch_bounds__(TPB, 1)
cmcd_fused(const float* __restrict__ particles, const float* __restrict__ noises,
           const float* __restrict__ grid_t, const float* __restrict__ eps,
           const float* __restrict__ means, const float* __restrict__ phase,
           const float* __restrict__ in_W, const float* __restrict__ in_b,
           const float* __restrict__ t_W1, const float* __restrict__ t_b1,
           const float* __restrict__ t_W2, const float* __restrict__ t_b2,
           const float* __restrict__ h_W, const float* __restrict__ h_b,
           const float* __restrict__ out_W, const float* __restrict__ out_b,
           float* __restrict__ out)
{
    extern __shared__ unsigned char smem_raw[];
    Smem* sm = reinterpret_cast<Smem*>(smem_raw);
    int blk = blockIdx.x, tid = threadIdx.x;
    int gtid = blk*TPB + tid;

    // ── S0: copy slice 0, zero both hists, temb (sin/cos), betas ──
    for (int idx = gtid; idx < Bp*Dd; idx += GRID*TPB) out[idx] = particles[idx];
    for (int idx = gtid; idx < 2*NBINS; idx += GRID*TPB) g_hist[0][idx] = 0;
    if (gtid < NBs*2*Cc){
        int idx = gtid;
        int s = idx >> 10, c = idx & 1023;
        float t = (float)s;
        int cc = (c < Cc) ? c : c - Cc;
        float coeff = 0.1f + (float)cc*(99.9f/511.0f);
        float e = coeff*t + phase[cc];
        g_temb[idx] = (c < Cc) ? sinf(e) : cosf(e);
    }
    if (gtid == 0){
        float cum = 0.f;
        g_betas[0] = 0.f;
        for (int j = 0; j < NBs; j++){
            float sg = 1.f/(1.f+expf(-grid_t[j]));
            cum += sg;
            g_betas[j+1] = cum;
        }
        float inv = 1.f/cum;
        for (int j = 1; j <= NBs; j++) g_betas[j] *= inv;
    }
    gridbar();

    // ── S1: t-MLP layer 1 (8-way K-split + shuffle reduce) ──
    {
        int oidx = gtid >> 3;       // 0..4095
        int sl   = gtid & 7;
        int s = oidx >> 9, c = oidx & 511;
        float acc = 0.f;
        const float* tb = g_temb + s*2*Cc;
        int kb = sl*128;
        #pragma unroll 4
        for (int k = kb; k < kb+128; k++) acc += tb[k]*t_W1[k*Cc + c];
        #pragma unroll
        for (int o = 1; o < 8; o <<= 1) acc += __shfl_xor_sync(0xffffffffu, acc, o);
        if (sl == 0) g_tg1[oidx] = gelu_t(acc + t_b1[c]);
    }
    gridbar();

    // ── S2: t-MLP layer 2 + in_b → fused input bias ──
    {
        int oidx = gtid >> 3;
        int sl   = gtid & 7;
        int s = oidx >> 9, c = oidx & 511;
        float acc = 0.f;
        const float* gb = g_tg1 + s*Cc;
        int kb = sl*64;
        #pragma unroll 4
        for (int k = kb; k < kb+64; k++) acc += gb[k]*t_W2[k*Cc + c];
        #pragma unroll
        for (int o = 1; o < 8; o <<= 1) acc += __shfl_xor_sync(0xffffffffu, acc, o);
        if (sl == 0) g_bias1[oidx] = acc + t_b2[c] + in_b[c];
    }
    gridbar();

    int m0 = (blk >> 4) * 64;     // 8 m-tiles of 64 rows
    int n0 = (blk & 15) * 32;     // 16 n-tiles of 32 cols

    for (int s = 0; s < NBs; s++){
        const float* x = out + (size_t)s*Bp*Dd;
        float* xn      = out + (size_t)(s+1)*Bp*Dd;
        int par = s & 1;

        // ── P1: input layer (K=64) + pairwise d2/hist ──
        gemm_tile_tc(x, Dd, in_W, Cc, m0, n0, 0, Dd, g_bias1 + s*Cc, 1, g_hA, Cc, sm);
        pairwise_tile(x, (blk>>3)*32, (blk&7)*64, g_hist[par], sm);
        gridbar();

        // ── P2-P4: hidden layers ──
        gemm_tile_tc(g_hA, Cc, h_W + 0*Cc*Cc, Cc, m0, n0, 0, Cc, h_b + 0*Cc, 1, g_hB, Cc, sm);
        gridbar();
        gemm_tile_tc(g_hB, Cc, h_W + 1*Cc*Cc, Cc, m0, n0, 0, Cc, h_b + 1*Cc, 1, g_hA, Cc, sm);
        gridbar();
        gemm_tile_tc(g_hA, Cc, h_W + 2*Cc*Cc, Cc, m0, n0, 0, Cc, h_b + 2*Cc, 1, g_hB, Cc, sm);
        gridbar();

        // ── P5: output layer split-K partials (across blocks) ──
        {
            int ksp = blk >> 4;            // 0..7 k-split
            int rem = blk & 15;
            int om0 = (rem >> 1) * 64;     // 8 m-tiles
            int on0 = (rem & 1) * 32;      // 2 n-tiles
            gemm_tile_tc(g_hB, Cc, out_W, Dd, om0, on0, ksp*64, 64, nullptr, 0,
                         g_sp + (size_t)ksp*Bp*Dd, Dd, sm);
        }
        gridbar();

        // ── P6: local median + fused Langevin update + zero next hist ──
        {
            float ht = median_local(g_hist[par], sm);
            float inv_ht = 1.f/ht;
            int p = tid >> 6;
            int d = tid & 63;
            int i = blk*4 + p;
            float dt = eps[0];
            float t = g_betas[s];
            float s2dt = sqrtf(2.f*dt);
            float xi_d = x[i*Dd + d];
            #pragma unroll
            for (int q = 0; q < 8; q++){
                int j = d + q*64;
                sm->u.w[p][j] = expf(-g_d2[i*Bp + j]*inv_ht);
            }
            if (d < MC){
                float sacc = 0.f;
                #pragma unroll 4
                for (int k = 0; k < Dd; k++){
                    float df = x[i*Dd + k] - means[d*Dd + k];
                    sacc += df*df;
                }
                sm->u.compm[p][d] = -0.5f*sacc;
            }
            __syncthreads();
            if (d == 0){
                float mx = sm->u.compm[p][0];
                for (int m = 1; m < MC; m++) mx = fmaxf(mx, sm->u.compm[p][m]);
                float se = 0.f;
                for (int m = 0; m < MC; m++){
                    float e = expf(sm->u.compm[p][m]-mx);
                    sm->u.wm[p][m] = e; se += e;
                }
                float inv = 1.f/se;
                for (int m = 0; m < MC; m++) sm->u.wm[p][m] *= inv;
            }
            __syncthreads();
            float wbar = 0.f;
            #pragma unroll
            for (int m = 0; m < MC; m++) wbar += sm->u.wm[p][m]*means[m*Dd + d];
            float r = 0.f;
            const float* wrow = sm->u.w[p];
            #pragma unroll 8
            for (int j = 0; j < Bp; j++)
                r += wrow[j]*(xi_d - x[j*Dd + d]);
            float score = out_b[d];
            #pragma unroll
            for (int ks = 0; ks < 8; ks++) score += g_sp[(size_t)ks*Bp*Dd + i*Dd + d];
            float drift = t*wbar - xi_d - score;
            float nv = noises[((size_t)s*Bp + i)*Dd + d];
            xn[i*Dd + d] = xi_d + dt*drift + s2dt*nv + 0.1f*dt*inv_ht*r;
            // zero the OTHER histogram (used next step); reads of hist[par] are done
            for (int idx = gtid; idx < NBINS; idx += GRID*TPB) g_hist[par^1][idx] = 0;
        }
        gridbar();
    }
}

extern "C" void kernel_launch(void* const* d_in, const int* in_sizes, int n_in,
                              void* d_out, int out_size){
    const float* particles = (const float*)d_in[0];
    const float* noises    = (const float*)d_in[1];
    const float* grid_t    = (const float*)d_in[2];
    const float* eps       = (const float*)d_in[3];
    const float* means     = (const float*)d_in[4];
    const float* phase     = (const float*)d_in[5];
    const float* in_W      = (const float*)d_in[6];
    const float* in_b      = (const float*)d_in[7];
    const float* t_W1      = (const float*)d_in[8];
    const float* t_b1      = (const float*)d_in[9];
    const float* t_W2      = (const float*)d_in[10];
    const float* t_b2      = (const float*)d_in[11];
    const float* h_W       = (const float*)d_in[12];
    const float* h_b       = (const float*)d_in[13];
    const float* out_W     = (const float*)d_in[14];
    const float* out_b     = (const float*)d_in[15];
    float* out = (float*)d_out;

    static int smem_set = -1;
    int smem_bytes = (int)sizeof(Smem);
    if (smem_set < 0){
        cudaFuncSetAttribute(cmcd_fused, cudaFuncAttributeMaxDynamicSharedMemorySize, smem_bytes);
        smem_set = 1;
    }

    cmcd_fused<<<GRID, TPB, smem_bytes>>>(particles, noises, grid_t, eps, means, phase,
                                          in_W, in_b, t_W1, t_b1, t_W2, t_b2,
                                          h_W, h_b, out_W, out_b, out);
}